// round 9
// baseline (speedup 1.0000x reference)
#include <cuda_runtime.h>

// NeRF importance sampler — search-free math (R6) in R7's execution shape.
//   inputs : rays_o[N,3], rays_d[N,3], z_vals[N,64] (sorted), weights[N,64]
//   outputs: pts[N,192,3] | z_all[N,192] | z_samples[N,128]  (flat concat)
//
// One warp per ray, 8 warps/block, forced 8 blocks/SM (regs <= 32).
// u_j = j/127 is uniform, so searchsorted(cdf,u_j) inverts analytically:
// boundary m -> B_m = min(ceil(127*cdf_m),128) = first sample at/above it.
// lo_j for all 128 samples = inclusive scan of a scatter histogram of B.
// The merge uses integer ranks (B) + one float compare per element; the two
// sides use complementary compares so positions always form a permutation.
// Phase 5 computes each output float4 directly from zal (2 scalar LDS +
// 6 FMA + 3-way select) with fully coalesced STG.128.

#define NS   64
#define NI   128
#define NT   192
#define WPB  8
#define WST  704

__global__ __launch_bounds__(256, 8)
void importance_sampler_kernel(const float* __restrict__ rays_o,
                               const float* __restrict__ rays_d,
                               const float* __restrict__ z_vals,
                               const float* __restrict__ weights,
                               float* __restrict__ out_pts,    // [N,192,3]
                               float* __restrict__ out_zall,   // [N,192]
                               float* __restrict__ out_zs,     // [N,128]
                               int n_rays)
{
    __shared__ __align__(16) float sbuf[WPB][WST];

    const int warp = threadIdx.x >> 5;
    const int lane = threadIdx.x & 31;
    const int ray  = blockIdx.x * WPB + warp;
    if (ray >= n_rays) return;

    float* buf = sbuf[warp];
    float* zv  = buf;                  // [0,64)
    float* cdf = buf + 64;             // [64,127) used (63 entries)
    float* mid = buf + 128;            // [128,191) used (63 entries)
    float* zs  = buf + 192;            // [192,320)
    float* zal = buf + 320;            // [320,512)
    int*   Bar = (int*)(buf + 512);    // [512,576) : B[0..63]
    int*   dmk = (int*)(buf + 576);    // [576,704) : marker histogram[128]

    // ---- Phase 1: load z_vals + weights, build cdf and B ------------------
    const float2 z2 = ((const float2*)(z_vals + (size_t)ray * NS))[lane];
    ((float2*)zv)[lane] = z2;

    const float2 w2 = ((const float2*)(weights + (size_t)ray * NS))[lane];
    const float wnx = __shfl_down_sync(0xffffffffu, w2.x, 1);   // wrow[2l+2]

    // zero marker histogram (visible after the syncwarp below)
    ((int4*)dmk)[lane] = make_int4(0, 0, 0, 0);

    // w[j] = weights[j+1] + 1e-5, j = 0..61; lane l<31 owns j=2l (wa), 2l+1 (wb)
    float wa = 0.f, wb = 0.f;
    if (lane < 31) {
        wa = w2.y + 1e-5f;
        wb = wnx  + 1e-5f;
    }
    const float local = wa + wb;
    float s = local;
    #pragma unroll
    for (int off = 1; off < 32; off <<= 1) {
        float up = __shfl_up_sync(0xffffffffu, s, off);
        if (lane >= off) s += up;
    }
    const float inv_total = 1.0f / __shfl_sync(0xffffffffu, s, 31);
    const float excl = s - local;

    int b1 = 128, b2 = 128;
    if (lane < 31) {
        const float c1 = (excl + wa) * inv_total;     // cdf[2l+1]
        const float c2 = (excl + local) * inv_total;  // cdf[2l+2]
        cdf[2 * lane + 1] = c1;
        cdf[2 * lane + 2] = c2;
        b1 = min((int)ceilf(c1 * 127.0f), 128);
        b2 = min((int)ceilf(c2 * 127.0f), 128);
        Bar[2 * lane + 1] = b1;
        Bar[2 * lane + 2] = b2;
    } else {
        cdf[0]  = 0.f;
        Bar[0]  = 0;
        Bar[63] = 128;
    }

    // ---- Phase 2: z_mid[k] = 0.5*(zv[k]+zv[k+1]), k = 0..62 ---------------
    const float znx = __shfl_down_sync(0xffffffffu, z2.x, 1);   // zv[2l+2]
    mid[2 * lane] = 0.5f * (z2.x + z2.y);                       // mid[62] at l=31
    if (lane < 31) mid[2 * lane + 1] = 0.5f * (z2.y + znx);
    __syncwarp();

    // ---- markers: one increment at each boundary's first sample index -----
    if (lane < 31) {
        if (b1 < 128) atomicAdd(&dmk[b1], 1);
        if (b2 < 128) atomicAdd(&dmk[b2], 1);
    }
    __syncwarp();

    // ---- Phase 3: scan -> lo_j for samples j = 4*lane + r, then interp ----
    const int4 dv = ((const int4*)dmk)[lane];
    const int p0 = dv.x;
    const int p1 = p0 + dv.y;
    const int p2 = p1 + dv.z;
    const int p3 = p2 + dv.w;
    int run = p3;
    #pragma unroll
    for (int off = 1; off < 32; off <<= 1) {
        int up = __shfl_up_sync(0xffffffffu, run, off);
        if (lane >= off) run += up;
    }
    const int base = run - p3;
    const int los[4] = { base + p0 + 1, base + p1 + 1, base + p2 + 1, base + p3 + 1 };

    const int j0 = 4 * lane;
    float vv[4];
    #pragma unroll
    for (int r = 0; r < 4; r++) {
        const float u = (float)(j0 + r) * (1.0f / 127.0f);
        const int lo    = los[r];
        const int below = lo - 1;
        const int above = min(lo, 62);
        const float cb = cdf[below];
        float denom = cdf[above] - cb;
        if (denom < 1e-5f) denom = 1.0f;
        const float tt = (u - cb) / denom;
        const float mb = mid[below];
        vv[r] = fmaf(tt, mid[above] - mb, mb);
    }
    const float4 v4 = make_float4(vv[0], vv[1], vv[2], vv[3]);
    ((float4*)zs)[lane] = v4;
    ((float4*)(out_zs + (size_t)ray * NI))[lane] = v4;          // coalesced

    // zs-side merge: pos = j + lo + (zv[lo] <= v)  (zv[0..lo-1] < v < zv[lo+1])
    #pragma unroll
    for (int r = 0; r < 4; r++) {
        const int lo = los[r];
        const int cnt = lo + (zv[lo] <= vv[r] ? 1 : 0);
        zal[j0 + r + cnt] = vv[r];
    }
    __syncwarp();

    // ---- Phase 4: zv-side merge. pos_i = i + B[i-1] + #{j in [B[i-1],B[i]) :
    //      zs[j] < zv[i]}  (samples with lo<=i-1 are < zv[i]; lo>=i+1 are >=)
    #pragma unroll
    for (int t = 0; t < 2; t++) {
        const int i = 2 * lane + t;
        const float v = t ? z2.y : z2.x;
        const int bprev = (i == 0) ? 0 : Bar[i - 1];
        const int bcur  = Bar[i];
        int cnt = bprev;
        for (int j = bprev; j < bcur; j++)
            if (zs[j] < v) cnt++;
        zal[i + cnt] = v;
    }
    __syncwarp();

    // ---- z_all out (float4, coalesced) ------------------------------------
    {
        float4* a4 = (float4*)(out_zall + (size_t)ray * NT);   // 48 x float4
        a4[lane] = ((const float4*)zal)[lane];
        if (lane < 16) a4[32 + lane] = ((const float4*)zal)[32 + lane];
    }

    // ---- Phase 5: pts directly from zal, fully coalesced STG.128 ----------
    const float ox = rays_o[3 * (size_t)ray + 0];
    const float oy = rays_o[3 * (size_t)ray + 1];
    const float oz = rays_o[3 * (size_t)ray + 2];
    const float dx = rays_d[3 * (size_t)ray + 0];
    const float dy = rays_d[3 * (size_t)ray + 1];
    const float dz = rays_d[3 * (size_t)ray + 2];

    float4* o4 = (float4*)(out_pts + (size_t)ray * (NT * 3));  // 144 x float4
    #pragma unroll
    for (int t = 0; t < 5; t++) {
        if (t < 4 || lane < 16) {
            const int m  = lane + 32 * t;          // output float4 id, 0..143
            const int r  = m % 3;                  // == (4m)%3 since 4 = 1 mod 3
            const int ka = (4 * m - r) / 3;        // first point touched
            const float za = zal[ka];
            const float zb = zal[ka + 1];          // ka+1 <= 191
            const float Ax = fmaf(dx, za, ox);
            const float Ay = fmaf(dy, za, oy);
            const float Az = fmaf(dz, za, oz);
            const float Bx = fmaf(dx, zb, ox);
            const float By = fmaf(dy, zb, oy);
            const float Bz = fmaf(dz, zb, oz);
            float4 o;
            if (r == 0)      o = make_float4(Ax, Ay, Az, Bx);
            else if (r == 1) o = make_float4(Ay, Az, Bx, By);
            else             o = make_float4(Az, Bx, By, Bz);
            o4[m] = o;                              // coalesced
        }
    }
}

extern "C" void kernel_launch(void* const* d_in, const int* in_sizes, int n_in,
                              void* d_out, int out_size)
{
    const float* rays_o  = (const float*)d_in[0];
    const float* rays_d  = (const float*)d_in[1];
    const float* z_vals  = (const float*)d_in[2];
    const float* weights = (const float*)d_in[3];

    const int n_rays = in_sizes[0] / 3;

    float* out_pts  = (float*)d_out;
    float* out_zall = out_pts + (size_t)n_rays * (NT * 3);
    float* out_zs   = out_zall + (size_t)n_rays * NT;

    const int blocks = (n_rays + WPB - 1) / WPB;
    importance_sampler_kernel<<<blocks, 256>>>(rays_o, rays_d, z_vals, weights,
                                               out_pts, out_zall, out_zs, n_rays);
}

// round 10
// speedup vs baseline: 1.0411x; 1.0411x over previous
#include <cuda_runtime.h>

// NeRF importance sampler — packed-interval formulation.
//   inputs : rays_o[N,3], rays_d[N,3], z_vals[N,64] (sorted), weights[N,64]
//   outputs: pts[N,192,3] | z_all[N,192] | z_samples[N,128]  (flat concat)
//
// One warp per ray, 8 warps/block, 8 blocks/SM. u_j = j/127 uniform, so
// searchsorted inverts analytically: boundary m -> B_m = min(ceil(127*cdf_m),128);
// lo_j = inclusive scan of a scatter histogram of B. Each CDF interval k
// carries a packed float4 ivl[k] = (cdf_k, mid_k, S_k, zv_{k+1}) with
// S_k = (mid_{k+1}-mid_k)/denom_k, so one LDS.128 per sample yields the
// interpolant AND the zs-side merge compare operand. cdf/mid/zv/B live only
// in registers + shuffles. Merge positions use complementary compares
// (zs < zv vs zv <= zs) -> always a permutation.

#define NS   64
#define NI   128
#define NT   192
#define WPB  8
#define WST  704   // floats/warp: ivl 256 | zs 128 | zal 192 | dmk 128

__global__ __launch_bounds__(256, 8)
void importance_sampler_kernel(const float* __restrict__ rays_o,
                               const float* __restrict__ rays_d,
                               const float* __restrict__ z_vals,
                               const float* __restrict__ weights,
                               float* __restrict__ out_pts,    // [N,192,3]
                               float* __restrict__ out_zall,   // [N,192]
                               float* __restrict__ out_zs,     // [N,128]
                               int n_rays)
{
    __shared__ __align__(16) float sbuf[WPB][WST];

    const int warp = threadIdx.x >> 5;
    const int lane = threadIdx.x & 31;
    const int ray  = blockIdx.x * WPB + warp;
    if (ray >= n_rays) return;

    float* buf = sbuf[warp];
    float* ivl = buf;                  // [0,256)  : 64 x float4 (63 used)
    float* zs  = buf + 256;            // [256,384)
    float* zal = buf + 384;            // [384,576)
    int*   dmk = (int*)(buf + 576);    // [576,704) : marker histogram[128]

    // ---- Phase 1: loads, CDF in registers, boundary ranks B ---------------
    const float2 z2 = ((const float2*)(z_vals + (size_t)ray * NS))[lane];
    const float2 w2 = ((const float2*)(weights + (size_t)ray * NS))[lane];
    const float wnx = __shfl_down_sync(0xffffffffu, w2.x, 1);   // wrow[2l+2]

    ((int4*)dmk)[lane] = make_int4(0, 0, 0, 0);                 // zero histogram

    // w[j] = weights[j+1]+1e-5, j=0..61; lane l<31 owns j=2l (wa), 2l+1 (wb)
    float wa = 0.f, wb = 0.f;
    if (lane < 31) {
        wa = w2.y + 1e-5f;
        wb = wnx  + 1e-5f;
    }
    const float local = wa + wb;
    float s = local;
    #pragma unroll
    for (int off = 1; off < 32; off <<= 1) {
        float up = __shfl_up_sync(0xffffffffu, s, off);
        if (lane >= off) s += up;
    }
    const float inv_total = 1.0f / __shfl_sync(0xffffffffu, s, 31);
    const float excl = s - local;

    // cdf[2l+1]=c1, cdf[2l+2]=c2 (lane<31); B defaults 128
    float c1 = 0.f, c2 = 0.f;
    int b1 = 128, b2 = 128;
    if (lane < 31) {
        c1 = (excl + wa) * inv_total;
        c2 = (excl + local) * inv_total;
        b1 = min((int)ceilf(c1 * 127.0f), 128);
        b2 = min((int)ceilf(c2 * 127.0f), 128);
    }

    // ---- Phase 2: mids in registers + packed interval table ---------------
    const float znx = __shfl_down_sync(0xffffffffu, z2.x, 1);   // zv[2l+2]
    const float m0 = 0.5f * (z2.x + z2.y);                      // mid[2l] (mid[62]@l31)
    const float m1 = 0.5f * (z2.y + znx);                       // mid[2l+1] (l<31)

    float cprev = __shfl_up_sync(0xffffffffu, c2, 1);           // cdf[2l]
    if (lane == 0) cprev = 0.f;
    const float mnext = __shfl_down_sync(0xffffffffu, m0, 1);   // mid[2l+2] (l<31)

    __syncwarp();   // dmk zero + prior-phase reuse visible before atomics

    // ivl[k] = (cdf_k, mid_k, S_k, zv_{k+1})
    {
        // k = 2l (all lanes; l==31 -> k=62: denom 0 -> guard -> S=0)
        float d0 = (lane < 31) ? (c1 - cprev) : 0.f;
        float n0 = (lane < 31) ? (m1 - m0)    : 0.f;
        if (d0 < 1e-5f) d0 = 1.0f;
        ((float4*)ivl)[2 * lane] = make_float4(cprev, m0, n0 / d0, z2.y);
        if (lane < 31) {
            float d1 = c2 - c1;
            float n1 = mnext - m1;
            if (d1 < 1e-5f) d1 = 1.0f;
            ((float4*)ivl)[2 * lane + 1] = make_float4(c1, m1, n1 / d1, znx);
        }
        // markers: one increment at each boundary's first sample index
        if (lane < 31) {
            if (b1 < 128) atomicAdd(&dmk[b1], 1);
            if (b2 < 128) atomicAdd(&dmk[b2], 1);
        }
    }
    __syncwarp();

    // ---- Phase 3: scan -> lo_j for j = 4*lane + r, interp + zs-side merge -
    const int4 dv = ((const int4*)dmk)[lane];
    const int p0 = dv.x;
    const int p1 = p0 + dv.y;
    const int p2 = p1 + dv.z;
    const int p3 = p2 + dv.w;
    int run = p3;
    #pragma unroll
    for (int off = 1; off < 32; off <<= 1) {
        int up = __shfl_up_sync(0xffffffffu, run, off);
        if (lane >= off) run += up;
    }
    const int base = run - p3;
    const int los[4] = { base + p0 + 1, base + p1 + 1, base + p2 + 1, base + p3 + 1 };

    const int j0 = 4 * lane;
    float vv[4];
    #pragma unroll
    for (int r = 0; r < 4; r++) {
        const float u  = (float)(j0 + r) * (1.0f / 127.0f);
        const int lo   = los[r];
        const float4 iv = ((const float4*)ivl)[lo - 1];   // (cdf_b, mid_b, S, zv[lo])
        const float v  = fmaf(u - iv.x, iv.z, iv.y);
        vv[r] = v;
        // zs-side merge: pos = j + lo + (zv[lo] <= v)
        const int cnt = lo + (iv.w <= v ? 1 : 0);
        zal[j0 + r + cnt] = v;
    }
    const float4 v4 = make_float4(vv[0], vv[1], vv[2], vv[3]);
    ((float4*)zs)[lane] = v4;
    ((float4*)(out_zs + (size_t)ray * NI))[lane] = v4;          // coalesced
    __syncwarp();

    // ---- Phase 4: zv-side merge. pos_i = i + B[i-1] + #{j in [B[i-1],B[i]):
    //      zs[j] < zv[i]}. B values arrive via shuffles (B[2l+1]=b1_l, B[2l+2]=b2_l).
    const int bp1 = __shfl_up_sync(0xffffffffu, b1, 1);   // B[2l-1]
    const int bp2 = __shfl_up_sync(0xffffffffu, b2, 1);   // B[2l]
    #pragma unroll
    for (int t = 0; t < 2; t++) {
        const int i = 2 * lane + t;
        const float v = t ? z2.y : z2.x;
        int bprev, bcur;
        if (t == 0) { bprev = (lane == 0) ? 0 : bp1;  bcur = (lane == 0) ? 0 : bp2; }
        else        { bprev = (lane == 0) ? 0 : bp2;  bcur = b1; }   // B[0]=0
        int cnt = bprev;
        for (int j = bprev; j < bcur; j++)
            if (zs[j] < v) cnt++;
        zal[i + cnt] = v;
    }
    __syncwarp();

    // ---- z_all out (float4, coalesced) ------------------------------------
    {
        float4* a4 = (float4*)(out_zall + (size_t)ray * NT);   // 48 x float4
        a4[lane] = ((const float4*)zal)[lane];
        if (lane < 16) a4[32 + lane] = ((const float4*)zal)[32 + lane];
    }

    // ---- Phase 5: pts directly from zal, fully coalesced STG.128 ----------
    const float ox = rays_o[3 * (size_t)ray + 0];
    const float oy = rays_o[3 * (size_t)ray + 1];
    const float oz = rays_o[3 * (size_t)ray + 2];
    const float dx = rays_d[3 * (size_t)ray + 0];
    const float dy = rays_d[3 * (size_t)ray + 1];
    const float dz = rays_d[3 * (size_t)ray + 2];

    float4* o4 = (float4*)(out_pts + (size_t)ray * (NT * 3));  // 144 x float4
    #pragma unroll
    for (int t = 0; t < 5; t++) {
        if (t < 4 || lane < 16) {
            const int m  = lane + 32 * t;          // output float4 id, 0..143
            const int r  = m % 3;                  // == (4m)%3 since 4 = 1 mod 3
            const int ka = (4 * m - r) / 3;        // first point touched
            const float za = zal[ka];
            const float zb = zal[ka + 1];          // ka+1 <= 191
            const float Ax = fmaf(dx, za, ox);
            const float Ay = fmaf(dy, za, oy);
            const float Az = fmaf(dz, za, oz);
            const float Bx = fmaf(dx, zb, ox);
            const float By = fmaf(dy, zb, oy);
            const float Bz = fmaf(dz, zb, oz);
            float4 o;
            if (r == 0)      o = make_float4(Ax, Ay, Az, Bx);
            else if (r == 1) o = make_float4(Ay, Az, Bx, By);
            else             o = make_float4(Az, Bx, By, Bz);
            o4[m] = o;                              // coalesced
        }
    }
}

extern "C" void kernel_launch(void* const* d_in, const int* in_sizes, int n_in,
                              void* d_out, int out_size)
{
    const float* rays_o  = (const float*)d_in[0];
    const float* rays_d  = (const float*)d_in[1];
    const float* z_vals  = (const float*)d_in[2];
    const float* weights = (const float*)d_in[3];

    const int n_rays = in_sizes[0] / 3;

    float* out_pts  = (float*)d_out;
    float* out_zall = out_pts + (size_t)n_rays * (NT * 3);
    float* out_zs   = out_zall + (size_t)n_rays * NT;

    const int blocks = (n_rays + WPB - 1) / WPB;
    importance_sampler_kernel<<<blocks, 256>>>(rays_o, rays_d, z_vals, weights,
                                               out_pts, out_zall, out_zs, n_rays);
}

// round 11
// speedup vs baseline: 1.1610x; 1.1151x over previous
#include <cuda_runtime.h>

// NeRF importance sampler — push-model (interval-owner) formulation.
//   inputs : rays_o[N,3], rays_d[N,3], z_vals[N,64] (sorted), weights[N,64]
//   outputs: pts[N,192,3] | z_all[N,192] | z_samples[N,128]  (flat concat)
//
// One warp per ray, 8 warps/block, 8 blocks/SM. u_j = j/127 is uniform, so
// interval k (between cdf_k and cdf_{k+1}) owns exactly samples
// j in [B_k, B_{k+1}), B_k = clamp(ceil(127*cdf_k), 0, 128). Lane l owns
// intervals 2l and 2l+1 with all parameters (cdf, mid, slope, right edge zv)
// in registers; it GENERATES its samples, scatters them into zs and directly
// into their merged position in zal (pos = j + lo + (zvR <= v)), counts
// #{v < zvR} in-flight, and places its right-edge z_val at
// k+1 + B_k + count_lt. Complementary compares (zvR <= v vs v < zvR) make
// the 192 positions a permutation. No histogram, no scan, no gathers.

#define NS   64
#define NI   128
#define NT   192
#define WPB  8

__global__ __launch_bounds__(256, 8)
void importance_sampler_kernel(const float* __restrict__ rays_o,
                               const float* __restrict__ rays_d,
                               const float* __restrict__ z_vals,
                               const float* __restrict__ weights,
                               float* __restrict__ out_pts,    // [N,192,3]
                               float* __restrict__ out_zall,   // [N,192]
                               float* __restrict__ out_zs,     // [N,128]
                               int n_rays)
{
    __shared__ __align__(16) float sbuf[WPB][320];   // zs 128 | zal 192

    const int warp = threadIdx.x >> 5;
    const int lane = threadIdx.x & 31;
    const int ray  = blockIdx.x * WPB + warp;
    if (ray >= n_rays) return;

    float* buf = sbuf[warp];
    float* zs  = buf;          // [0,128)
    float* zal = buf + 128;    // [128,320)

    // ---- Phase 1: loads + CDF scan (all in registers) ---------------------
    const float2 z2 = ((const float2*)(z_vals + (size_t)ray * NS))[lane];
    const float2 w2 = ((const float2*)(weights + (size_t)ray * NS))[lane];
    const float wnx = __shfl_down_sync(0xffffffffu, w2.x, 1);   // wrow[2l+2]

    // w[j] = weights[j+1]+1e-5, j=0..61; lane l<31 owns j=2l (wa), 2l+1 (wb)
    float wa = 0.f, wb = 0.f;
    if (lane < 31) {
        wa = w2.y + 1e-5f;
        wb = wnx  + 1e-5f;
    }
    const float local = wa + wb;
    float s = local;
    #pragma unroll
    for (int off = 1; off < 32; off <<= 1) {
        float up = __shfl_up_sync(0xffffffffu, s, off);
        if (lane >= off) s += up;
    }
    const float inv_total = 1.0f / __shfl_sync(0xffffffffu, s, 31);
    const float excl = s - local;

    // cdf[2l+1] = c1, cdf[2l+2] = c2 (valid for lane<31)
    float c1 = 0.f, c2 = 0.f;
    if (lane < 31) {
        c1 = (excl + wa) * inv_total;
        c2 = (excl + local) * inv_total;
    }

    // ---- Phase 2: per-lane interval parameters (registers only) -----------
    const float znx = __shfl_down_sync(0xffffffffu, z2.x, 1);   // zv[2l+2]
    const float m0  = 0.5f * (z2.x + z2.y);                     // mid[2l]
    const float m1  = 0.5f * (z2.y + znx);                      // mid[2l+1] (l<31)
    float cprev = __shfl_up_sync(0xffffffffu, c2, 1);           // cdf[2l]
    if (lane == 0) cprev = 0.f;
    const float mnext = __shfl_down_sync(0xffffffffu, m0, 1);   // mid[2l+2] (l<31)

    // Sample-range boundaries B (monotone since cdf strictly increases)
    const int bA = min((int)ceilf(cprev * 127.0f), 128);        // B[2l]
    int bB = 128, bC = 128;                                     // lane 31: A=[bA,128)
    float SA = 0.f, SB = 0.f;                                   // lane 31: v = mid[62]
    if (lane < 31) {
        bB = min((int)ceilf(c1 * 127.0f), 128);                 // B[2l+1]
        bC = min((int)ceilf(c2 * 127.0f), 128);                 // B[2l+2]
        float dA = c1 - cprev; if (dA < 1e-5f) dA = 1.0f;
        float dB = c2 - c1;    if (dB < 1e-5f) dB = 1.0f;
        SA = (m1 - m0) / dA;
        SB = (mnext - m1) / dB;
    }

    // ---- Phase 3: generate samples, scatter into zs and merged zal --------
    if (lane == 0) zal[0] = z2.x;              // zv[0] always ranks first

    // interval k = 2l: samples [bA, bB), right edge zv[2l+1] = z2.y, lo = 2l+1
    {
        int cnt_ge = 0;
        for (int j = bA; j < bB; j++) {
            const float u = (float)j * (1.0f / 127.0f);
            const float v = fmaf(u - cprev, SA, m0);
            zs[j] = v;
            const int ge = (z2.y <= v) ? 1 : 0;
            cnt_ge += ge;
            zal[j + 2 * lane + 1 + ge] = v;
        }
        // place zv[2l+1]: pos = (2l+1) + B[2l] + #{v < zv[2l+1]}
        zal[2 * lane + 1 + bA + (bB - bA) - cnt_ge] = z2.y;
    }
    // interval k = 2l+1 (lane<31): samples [bB, bC), right edge zv[2l+2] = znx
    {
        int cnt_ge = 0;
        for (int j = bB; j < bC; j++) {
            const float u = (float)j * (1.0f / 127.0f);
            const float v = fmaf(u - c1, SB, m1);
            zs[j] = v;
            const int ge = (znx <= v) ? 1 : 0;
            cnt_ge += ge;
            zal[j + 2 * lane + 2 + ge] = v;
        }
        if (lane < 31)
            zal[2 * lane + 2 + bB + (bC - bB) - cnt_ge] = znx;
    }
    __syncwarp();

    // ---- z_samples + z_all out (float4, coalesced) ------------------------
    {
        float4* s4 = (float4*)(out_zs + (size_t)ray * NI);     // 32 x float4
        s4[lane] = ((const float4*)zs)[lane];

        float4* a4 = (float4*)(out_zall + (size_t)ray * NT);   // 48 x float4
        a4[lane] = ((const float4*)zal)[lane];
        if (lane < 16) a4[32 + lane] = ((const float4*)zal)[32 + lane];
    }

    // ---- Phase 5: pts directly from zal, fully coalesced STG.128 ----------
    const float ox = rays_o[3 * (size_t)ray + 0];
    const float oy = rays_o[3 * (size_t)ray + 1];
    const float oz = rays_o[3 * (size_t)ray + 2];
    const float dx = rays_d[3 * (size_t)ray + 0];
    const float dy = rays_d[3 * (size_t)ray + 1];
    const float dz = rays_d[3 * (size_t)ray + 2];

    float4* o4 = (float4*)(out_pts + (size_t)ray * (NT * 3));  // 144 x float4
    #pragma unroll
    for (int t = 0; t < 5; t++) {
        if (t < 4 || lane < 16) {
            const int m  = lane + 32 * t;          // output float4 id, 0..143
            const int r  = m % 3;                  // == (4m)%3 since 4 = 1 mod 3
            const int ka = (4 * m - r) / 3;        // first point touched
            const float za = zal[ka];
            const float zb = zal[ka + 1];          // ka+1 <= 191
            const float Ax = fmaf(dx, za, ox);
            const float Ay = fmaf(dy, za, oy);
            const float Az = fmaf(dz, za, oz);
            const float Bx = fmaf(dx, zb, ox);
            const float By = fmaf(dy, zb, oy);
            const float Bz = fmaf(dz, zb, oz);
            float4 o;
            if (r == 0)      o = make_float4(Ax, Ay, Az, Bx);
            else if (r == 1) o = make_float4(Ay, Az, Bx, By);
            else             o = make_float4(Az, Bx, By, Bz);
            o4[m] = o;                              // coalesced
        }
    }
}

extern "C" void kernel_launch(void* const* d_in, const int* in_sizes, int n_in,
                              void* d_out, int out_size)
{
    const float* rays_o  = (const float*)d_in[0];
    const float* rays_d  = (const float*)d_in[1];
    const float* z_vals  = (const float*)d_in[2];
    const float* weights = (const float*)d_in[3];

    const int n_rays = in_sizes[0] / 3;

    float* out_pts  = (float*)d_out;
    float* out_zall = out_pts + (size_t)n_rays * (NT * 3);
    float* out_zs   = out_zall + (size_t)n_rays * NT;

    const int blocks = (n_rays + WPB - 1) / WPB;
    importance_sampler_kernel<<<blocks, 256>>>(rays_o, rays_d, z_vals, weights,
                                               out_pts, out_zall, out_zs, n_rays);
}